// round 13
// baseline (speedup 1.0000x reference)
#include <cuda_runtime.h>
#include <math.h>

#define BB   256
#define SS   196
#define RNN  1024
#define ATTH 512
#define KSPLIT 16
#define KCHUNK 64    // RNN / KSPLIT
#define SQ   49      // SS / 4

// Split-K partials for att_h = h @ w_h2att^T (bias folded in later).
__device__ float g_atth_part[KSPLIT * BB * ATTH];   // 8 MB
// Raw (pre-softmax) scores.
__device__ float g_scores[BB * SS];                 // 200 KB
// Per-batch completion flags for intra-kernel pipelining (zeroed by gemm).
__device__ int g_flag[BB];

// Fast accurate tanh: tanh(x) = 1 - 2/(exp(2x)+1); 2 MUFU, ~1e-7 abs err.
__device__ __forceinline__ float fast_tanhf(float x) {
  float e;
  asm("ex2.approx.f32 %0, %1;" : "=f"(e) : "f"(x * 2.885390081777927f));
  float r;
  asm("rcp.approx.f32 %0, %1;" : "=f"(r) : "f"(e + 1.0f));
  return fmaf(-2.0f, r, 1.0f);
}

// ---------------------------------------------------------------------------
// Kernel 1: split-K GEMM, 32(m) x 64(n) x 64(k), broadcast A microtile,
// XOR-swizzled smem. Also zeroes the pipeline flags for this run.
// Grid: (ATTH/64, BB/32, KSPLIT) = (8, 8, 16) = 1024 blocks, 256 threads.
// ---------------------------------------------------------------------------
__global__ __launch_bounds__(256) void gemm_atth_kernel(
    const float* __restrict__ h, const float* __restrict__ w) {
  const int n0 = blockIdx.x * 64;
  const int m0 = blockIdx.y * 32;
  const int k0 = blockIdx.z * KCHUNK;
  const int t  = threadIdx.x;        // 0..255

  // Reset pipeline flags (this kernel completes before the pipeline kernel).
  if (blockIdx.x == 0 && blockIdx.y == 0 && blockIdx.z == 0) g_flag[t] = 0;

  __shared__ float As[KCHUNK][32];   // [k][m], phys m = m ^ ((k>>3)<<2)
  __shared__ float Bs[KCHUNK][64];   // [k][n], phys n = n ^ ((k>>2&7)<<3)

  // ---- Load A tile (32m x 64k), transposed+swizzled. 8 floats/thread. ----
  {
    const int r  = t >> 3;           // m row 0..31
    const int c0 = (t & 7) * 8;      // k base; (c>>3)&7 == t&7 for all 8 c
    const int pa = r ^ ((t & 7) << 2);
    const float* src = h + (size_t)(m0 + r) * RNN + k0 + c0;
    const float4 v0 = *(const float4*)(src);
    const float4 v1 = *(const float4*)(src + 4);
    As[c0 + 0][pa] = v0.x; As[c0 + 1][pa] = v0.y;
    As[c0 + 2][pa] = v0.z; As[c0 + 3][pa] = v0.w;
    As[c0 + 4][pa] = v1.x; As[c0 + 5][pa] = v1.y;
    As[c0 + 6][pa] = v1.z; As[c0 + 7][pa] = v1.w;
  }
  // ---- Load B tile (64n x 64k), transposed+swizzled. 16 floats/thread. ----
  {
    const int r  = t >> 2;           // n row 0..63
    const int c0 = (t & 3) * 4;      // k base
    const float* src = w + (size_t)(n0 + r) * RNN + k0;
#pragma unroll
    for (int i = 0; i < 4; i++) {
      const int c  = c0 + i * 16;
      const int pb = r ^ ((((t & 3) + 4 * i) & 7) << 3);
      const float4 v = *(const float4*)(src + c);
      Bs[c + 0][pb] = v.x; Bs[c + 1][pb] = v.y;
      Bs[c + 2][pb] = v.z; Bs[c + 3][pb] = v.w;
    }
  }
  __syncthreads();

  const int warp = t >> 5;
  const int lane = t & 31;
  const int w4   = warp * 4;
  const int l2   = lane * 2;

  unsigned long long acc[2][2] = {{0ull, 0ull}, {0ull, 0ull}};

#pragma unroll 16
  for (int k = 0; k < KCHUNK; k++) {
    const int swa = ((k >> 3) & 7) << 2;
    const int swb = ((k >> 2) & 7) << 3;
    const float4 a = *(const float4*)&As[k][w4 ^ swa];  // broadcast LDS.128
    const float2 b = *(const float2*)&Bs[k][l2 ^ swb];  // conflict-free LDS.64
    unsigned long long a01, a23, b0, b1;
    asm("mov.b64 %0, {%1, %2};" : "=l"(a01) : "r"(__float_as_uint(a.x)), "r"(__float_as_uint(a.y)));
    asm("mov.b64 %0, {%1, %2};" : "=l"(a23) : "r"(__float_as_uint(a.z)), "r"(__float_as_uint(a.w)));
    asm("mov.b64 %0, {%1, %1};" : "=l"(b0) : "r"(__float_as_uint(b.x)));
    asm("mov.b64 %0, {%1, %1};" : "=l"(b1) : "r"(__float_as_uint(b.y)));
    asm("fma.rn.f32x2 %0, %1, %2, %0;" : "+l"(acc[0][0]) : "l"(a01), "l"(b0));
    asm("fma.rn.f32x2 %0, %1, %2, %0;" : "+l"(acc[0][1]) : "l"(a23), "l"(b0));
    asm("fma.rn.f32x2 %0, %1, %2, %0;" : "+l"(acc[1][0]) : "l"(a01), "l"(b1));
    asm("fma.rn.f32x2 %0, %1, %2, %0;" : "+l"(acc[1][1]) : "l"(a23), "l"(b1));
  }

  float* dst = g_atth_part + (size_t)blockIdx.z * BB * ATTH;
#pragma unroll
  for (int i = 0; i < 4; i++) {
    const int p = i >> 1, hi = i & 1;
    float2 o;
    o.x = __uint_as_float(hi ? (unsigned)(acc[0][p] >> 32) : (unsigned)acc[0][p]);
    o.y = __uint_as_float(hi ? (unsigned)(acc[1][p] >> 32) : (unsigned)acc[1][p]);
    *(float2*)(dst + (size_t)(m0 + w4 + i) * ATTH + n0 + l2) = o;
  }
}

// ---------------------------------------------------------------------------
// Kernel 2: pipelined scores + softmax/weighted-sum in ONE launch.
//   Blocks [0,1024):    scores for (b = bid/4, q = bid%4)  -> flag[b]++
//   Blocks [1024,2048): wait flag[b]==4, softmax, stream att_feats chunk.
// Deadlock-free: consumers have strictly larger block ids than producers;
// the work distributor issues CTAs in bid order and all producers fit
// on-chip simultaneously (1024 < ~1184 resident capacity).
// COHERENCE: consumers read g_scores with __ldcg (L2-only). g_scores rows
// are not line-aligned, so a .ca load could cache a line straddling two
// batches before the second batch's scores land; L1 is not coherent across
// SMs, so the flag protocol alone cannot protect .ca loads.
// ---------------------------------------------------------------------------
__global__ __launch_bounds__(256) void attn_pipeline_kernel(
    const float* __restrict__ p_att,
    const float* __restrict__ b_h2att,
    const float* __restrict__ w_alpha,
    const float* __restrict__ att_feats,
    float* __restrict__ out) {
  const int bid  = blockIdx.x;
  const int tid  = threadIdx.x;
  const int warp = tid >> 5;
  const int lane = tid & 31;

  if (bid < BB * 4) {
    // ==================== scores producer ====================
    __shared__ __align__(16) float sh_atth[ATTH];
    __shared__ __align__(16) float sh_wa[ATTH];
    const int b = bid >> 2;
    const int q = bid & 3;

#pragma unroll
    for (int a = tid; a < ATTH; a += 256) {
      float v = b_h2att[a];
#pragma unroll
      for (int z = 0; z < KSPLIT; z++)
        v += g_atth_part[(size_t)z * BB * ATTH + (size_t)b * ATTH + a];
      sh_atth[a] = v;
      sh_wa[a] = w_alpha[a];
    }
    __syncthreads();

    const float* pbase = p_att + (size_t)b * SS * ATTH + (size_t)q * SQ * ATTH;
    for (int sl = warp; sl < SQ; sl += 8) {
      const float* row = pbase + (size_t)sl * ATTH;
      float acc = 0.f;
#pragma unroll
      for (int i = 0; i < 4; i++) {
        const int a = i * 128 + lane * 4;
        const float4 p  = *(const float4*)(row + a);
        const float4 ah = *(const float4*)(sh_atth + a);
        const float4 wa = *(const float4*)(sh_wa + a);
        acc = fmaf(fast_tanhf(p.x + ah.x), wa.x, acc);
        acc = fmaf(fast_tanhf(p.y + ah.y), wa.y, acc);
        acc = fmaf(fast_tanhf(p.z + ah.z), wa.z, acc);
        acc = fmaf(fast_tanhf(p.w + ah.w), wa.w, acc);
      }
#pragma unroll
      for (int off = 16; off > 0; off >>= 1)
        acc += __shfl_xor_sync(0xffffffffu, acc, off);
      if (lane == 0) g_scores[(size_t)b * SS + q * SQ + sl] = acc;
    }

    __syncthreads();                      // all warps' score stores issued
    if (tid == 0) {
      __threadfence();                    // release: scores visible at L2
      atomicAdd(&g_flag[b], 1);
    }
  } else {
    // ==================== wsum consumer ====================
    __shared__ float sh_w[SS];
    __shared__ float red[8];
    const int cb = bid - BB * 4;
    const int b  = cb >> 2;
    const int q  = cb & 3;

    if (tid == 0) {
      while (atomicAdd(&g_flag[b], 0) < 4) { __nanosleep(64); }
      __threadfence();                    // acquire
    }
    __syncthreads();

    // --- softmax over 196 scores (L2-only loads: L1 not coherent) ---
    const float v = (tid < SS) ? __ldcg(&g_scores[(size_t)b * SS + tid])
                               : -INFINITY;

    float m = v;
#pragma unroll
    for (int off = 16; off > 0; off >>= 1)
      m = fmaxf(m, __shfl_xor_sync(0xffffffffu, m, off));
    if (lane == 0) red[warp] = m;
    __syncthreads();
    m = red[0];
#pragma unroll
    for (int i = 1; i < 8; i++) m = fmaxf(m, red[i]);
    __syncthreads();

    const float e = (tid < SS) ? __expf(v - m) : 0.f;
    float sum = e;
#pragma unroll
    for (int off = 16; off > 0; off >>= 1)
      sum += __shfl_xor_sync(0xffffffffu, sum, off);
    if (lane == 0) red[warp] = sum;
    __syncthreads();
    float tot = red[0];
#pragma unroll
    for (int i = 1; i < 8; i++) tot += red[i];
    const float inv = 1.f / tot;
    if (tid < SS) sh_w[tid] = e * inv;
    __syncthreads();

    // --- stream att_feats: 196 coalesced scalar loads per thread ---
    const int d = q * 256 + tid;
    const float* ab = att_feats + (size_t)b * SS * RNN + d;
    float acc = 0.f;
#pragma unroll 4
    for (int s = 0; s < SS; s++)
      acc = fmaf(sh_w[s], ab[(size_t)s * RNN], acc);

    out[(size_t)b * RNN + d] = acc;
  }
}

// ---------------------------------------------------------------------------
// Launch. Inputs: h, att_feats, p_att_feats, w_h2att, b_h2att, w_alpha,
// b_alpha (unused: softmax shift-invariant).
// ---------------------------------------------------------------------------
extern "C" void kernel_launch(void* const* d_in, const int* in_sizes, int n_in,
                              void* d_out, int out_size) {
  (void)in_sizes; (void)n_in; (void)out_size;
  const float* h         = (const float*)d_in[0];
  const float* att_feats = (const float*)d_in[1];
  const float* p_att     = (const float*)d_in[2];
  const float* w_h2att   = (const float*)d_in[3];
  const float* b_h2att   = (const float*)d_in[4];
  const float* w_alpha   = (const float*)d_in[5];
  float* out = (float*)d_out;

  dim3 g1(ATTH / 64, BB / 32, KSPLIT);      // (8, 8, 16) = 1024 blocks
  gemm_atth_kernel<<<g1, 256>>>(h, w_h2att);
  attn_pipeline_kernel<<<BB * 8, 256>>>(p_att, b_h2att, w_alpha, att_feats, out);
}

// round 14
// speedup vs baseline: 1.3409x; 1.3409x over previous
#include <cuda_runtime.h>
#include <math.h>

#define BB   256
#define SS   196
#define RNN  1024
#define ATTH 512
#define KSPLIT 16
#define KCHUNK 64    // RNN / KSPLIT
#define SQ   49      // SS / 4

// Split-K partials for att_h = h @ w_h2att^T (bias folded in later).
__device__ float g_atth_part[KSPLIT * BB * ATTH];   // 8 MB
// Raw (pre-softmax) scores.
__device__ float g_scores[BB * SS];                 // 200 KB

// Fast accurate tanh: tanh(x) = 1 - 2/(exp(2x)+1); 2 MUFU, ~1e-7 abs err.
__device__ __forceinline__ float fast_tanhf(float x) {
  float e;
  asm("ex2.approx.f32 %0, %1;" : "=f"(e) : "f"(x * 2.885390081777927f));
  float r;
  asm("rcp.approx.f32 %0, %1;" : "=f"(r) : "f"(e + 1.0f));
  return fmaf(-2.0f, r, 1.0f);
}

// ---------------------------------------------------------------------------
// Kernel 1: split-K GEMM, 32(m) x 64(n) x 64(k), broadcast A microtile,
// XOR-swizzled smem (conflict-free STS both tiles; A main-loop read is a
// warp-uniform broadcast, B read a bank permutation).
// Grid: (ATTH/64, BB/32, KSPLIT) = (8, 8, 16) = 1024 blocks, 256 threads.
// ---------------------------------------------------------------------------
__global__ __launch_bounds__(256) void gemm_atth_kernel(
    const float* __restrict__ h, const float* __restrict__ w) {
  const int n0 = blockIdx.x * 64;
  const int m0 = blockIdx.y * 32;
  const int k0 = blockIdx.z * KCHUNK;
  const int t  = threadIdx.x;        // 0..255

  __shared__ float As[KCHUNK][32];   // [k][m], phys m = m ^ ((k>>3)<<2)
  __shared__ float Bs[KCHUNK][64];   // [k][n], phys n = n ^ ((k>>2&7)<<3)

  // ---- Load A tile (32m x 64k), transposed+swizzled. 8 floats/thread. ----
  {
    const int r  = t >> 3;           // m row 0..31
    const int c0 = (t & 7) * 8;      // k base; (c>>3)&7 == t&7 for all 8 c
    const int pa = r ^ ((t & 7) << 2);
    const float* src = h + (size_t)(m0 + r) * RNN + k0 + c0;
    const float4 v0 = *(const float4*)(src);
    const float4 v1 = *(const float4*)(src + 4);
    As[c0 + 0][pa] = v0.x; As[c0 + 1][pa] = v0.y;
    As[c0 + 2][pa] = v0.z; As[c0 + 3][pa] = v0.w;
    As[c0 + 4][pa] = v1.x; As[c0 + 5][pa] = v1.y;
    As[c0 + 6][pa] = v1.z; As[c0 + 7][pa] = v1.w;
  }
  // ---- Load B tile (64n x 64k), transposed+swizzled. 16 floats/thread. ----
  {
    const int r  = t >> 2;           // n row 0..63
    const int c0 = (t & 3) * 4;      // k base
    const float* src = w + (size_t)(n0 + r) * RNN + k0;
#pragma unroll
    for (int i = 0; i < 4; i++) {
      const int c  = c0 + i * 16;
      const int pb = r ^ ((((t & 3) + 4 * i) & 7) << 3);
      const float4 v = *(const float4*)(src + c);
      Bs[c + 0][pb] = v.x; Bs[c + 1][pb] = v.y;
      Bs[c + 2][pb] = v.z; Bs[c + 3][pb] = v.w;
    }
  }
  __syncthreads();

  const int warp = t >> 5;
  const int lane = t & 31;
  const int w4   = warp * 4;
  const int l2   = lane * 2;

  unsigned long long acc[2][2] = {{0ull, 0ull}, {0ull, 0ull}};

#pragma unroll 16
  for (int k = 0; k < KCHUNK; k++) {
    const int swa = ((k >> 3) & 7) << 2;
    const int swb = ((k >> 2) & 7) << 3;
    const float4 a = *(const float4*)&As[k][w4 ^ swa];  // broadcast LDS.128
    const float2 b = *(const float2*)&Bs[k][l2 ^ swb];  // conflict-free LDS.64
    unsigned long long a01, a23, b0, b1;
    asm("mov.b64 %0, {%1, %2};" : "=l"(a01) : "r"(__float_as_uint(a.x)), "r"(__float_as_uint(a.y)));
    asm("mov.b64 %0, {%1, %2};" : "=l"(a23) : "r"(__float_as_uint(a.z)), "r"(__float_as_uint(a.w)));
    asm("mov.b64 %0, {%1, %1};" : "=l"(b0) : "r"(__float_as_uint(b.x)));
    asm("mov.b64 %0, {%1, %1};" : "=l"(b1) : "r"(__float_as_uint(b.y)));
    asm("fma.rn.f32x2 %0, %1, %2, %0;" : "+l"(acc[0][0]) : "l"(a01), "l"(b0));
    asm("fma.rn.f32x2 %0, %1, %2, %0;" : "+l"(acc[0][1]) : "l"(a23), "l"(b0));
    asm("fma.rn.f32x2 %0, %1, %2, %0;" : "+l"(acc[1][0]) : "l"(a01), "l"(b1));
    asm("fma.rn.f32x2 %0, %1, %2, %0;" : "+l"(acc[1][1]) : "l"(a23), "l"(b1));
  }

  float* dst = g_atth_part + (size_t)blockIdx.z * BB * ATTH;
#pragma unroll
  for (int i = 0; i < 4; i++) {
    const int p = i >> 1, hi = i & 1;
    float2 o;
    o.x = __uint_as_float(hi ? (unsigned)(acc[0][p] >> 32) : (unsigned)acc[0][p]);
    o.y = __uint_as_float(hi ? (unsigned)(acc[1][p] >> 32) : (unsigned)acc[1][p]);
    *(float2*)(dst + (size_t)(m0 + w4 + i) * ATTH + n0 + l2) = o;
  }
}

// ---------------------------------------------------------------------------
// Kernel 2: raw scores (PDL secondary of gemm).
//   scores[b,s] = sum_a tanh(p_att[b,s,a] + att_h[b,a] + bias[a]) * w_alpha[a]
// Grid: (BB, 4) = 1024 blocks, 256 threads. Block (b,q) handles 49 s-rows.
// w_alpha/bias staging is GEMM-independent and runs before the grid-dep sync.
// ---------------------------------------------------------------------------
__global__ __launch_bounds__(256) void scores_kernel(
    const float* __restrict__ p_att,
    const float* __restrict__ b_h2att,
    const float* __restrict__ w_alpha) {
  __shared__ __align__(16) float sh_atth[ATTH];
  __shared__ __align__(16) float sh_wa[ATTH];

  const int b    = blockIdx.x;
  const int q    = blockIdx.y;
  const int tid  = threadIdx.x;
  const int warp = tid >> 5;
  const int lane = tid & 31;

  // Independent prologue (overlaps with gemm tail under PDL).
#pragma unroll
  for (int a = tid; a < ATTH; a += 256) {
    sh_atth[a] = b_h2att[a];
    sh_wa[a]   = w_alpha[a];
  }

#if defined(__CUDA_ARCH__)
  cudaGridDependencySynchronize();   // gemm results now visible
#endif

#pragma unroll
  for (int a = tid; a < ATTH; a += 256) {
    float v = sh_atth[a];
#pragma unroll
    for (int z = 0; z < KSPLIT; z++)
      v += g_atth_part[(size_t)z * BB * ATTH + (size_t)b * ATTH + a];
    sh_atth[a] = v;
  }
  __syncthreads();

  const float* pbase = p_att + (size_t)b * SS * ATTH + (size_t)q * SQ * ATTH;
  for (int sl = warp; sl < SQ; sl += 8) {
    const float* row = pbase + (size_t)sl * ATTH;
    float acc = 0.f;
#pragma unroll
    for (int i = 0; i < 4; i++) {
      const int a = i * 128 + lane * 4;
      const float4 p  = *(const float4*)(row + a);
      const float4 ah = *(const float4*)(sh_atth + a);
      const float4 wa = *(const float4*)(sh_wa + a);
      acc = fmaf(fast_tanhf(p.x + ah.x), wa.x, acc);
      acc = fmaf(fast_tanhf(p.y + ah.y), wa.y, acc);
      acc = fmaf(fast_tanhf(p.z + ah.z), wa.z, acc);
      acc = fmaf(fast_tanhf(p.w + ah.w), wa.w, acc);
    }
#pragma unroll
    for (int off = 16; off > 0; off >>= 1)
      acc += __shfl_xor_sync(0xffffffffu, acc, off);
    if (lane == 0) g_scores[(size_t)b * SS + q * SQ + sl] = acc;
  }
}

// ---------------------------------------------------------------------------
// Kernel 3: softmax prologue + weighted sum (PDL secondary of scores).
//   out[b, q*256+t] = sum_s softmax(scores[b])[s] * att_feats[b,s,q*256+t]
// Grid: (BB, 4) = 1024 blocks, 256 threads, 1 output dim per thread.
// ---------------------------------------------------------------------------
__global__ __launch_bounds__(256) void wsum_kernel(
    const float* __restrict__ att_feats,
    float* __restrict__ out) {
  __shared__ float sh_w[SS];
  __shared__ float red[8];

  const int b    = blockIdx.x;
  const int q    = blockIdx.y;
  const int tid  = threadIdx.x;
  const int warp = tid >> 5;
  const int lane = tid & 31;

#if defined(__CUDA_ARCH__)
  cudaGridDependencySynchronize();   // scores now visible
#endif

  // --- softmax over 196 scores ---
  const float v = (tid < SS) ? g_scores[(size_t)b * SS + tid] : -INFINITY;

  float m = v;
#pragma unroll
  for (int off = 16; off > 0; off >>= 1)
    m = fmaxf(m, __shfl_xor_sync(0xffffffffu, m, off));
  if (lane == 0) red[warp] = m;
  __syncthreads();
  m = red[0];
#pragma unroll
  for (int i = 1; i < 8; i++) m = fmaxf(m, red[i]);
  __syncthreads();

  const float e = (tid < SS) ? __expf(v - m) : 0.f;
  float sum = e;
#pragma unroll
  for (int off = 16; off > 0; off >>= 1)
    sum += __shfl_xor_sync(0xffffffffu, sum, off);
  if (lane == 0) red[warp] = sum;
  __syncthreads();
  float tot = red[0];
#pragma unroll
  for (int i = 1; i < 8; i++) tot += red[i];
  const float inv = 1.f / tot;
  if (tid < SS) sh_w[tid] = e * inv;
  __syncthreads();

  // --- stream att_feats: 196 coalesced scalar loads per thread ---
  const int d = q * 256 + tid;
  const float* ab = att_feats + (size_t)b * SS * RNN + d;
  float acc = 0.f;
#pragma unroll 4
  for (int s = 0; s < SS; s++)
    acc = fmaf(sh_w[s], ab[(size_t)s * RNN], acc);

  out[(size_t)b * RNN + d] = acc;
}

// ---------------------------------------------------------------------------
// Launch. Inputs: h, att_feats, p_att_feats, w_h2att, b_h2att, w_alpha,
// b_alpha (unused: softmax shift-invariant). scores/wsum launched with
// programmatic stream serialization (PDL) to overlap launch+drain with the
// predecessor's tail.
// ---------------------------------------------------------------------------
extern "C" void kernel_launch(void* const* d_in, const int* in_sizes, int n_in,
                              void* d_out, int out_size) {
  (void)in_sizes; (void)n_in; (void)out_size;
  const float* h         = (const float*)d_in[0];
  const float* att_feats = (const float*)d_in[1];
  const float* p_att     = (const float*)d_in[2];
  const float* w_h2att   = (const float*)d_in[3];
  const float* b_h2att   = (const float*)d_in[4];
  const float* w_alpha   = (const float*)d_in[5];
  float* out = (float*)d_out;

  dim3 g1(ATTH / 64, BB / 32, KSPLIT);      // (8, 8, 16) = 1024 blocks
  gemm_atth_kernel<<<g1, 256>>>(h, w_h2att);

  cudaLaunchAttribute attr[1];
  attr[0].id = cudaLaunchAttributeProgrammaticStreamSerialization;
  attr[0].val.programmaticStreamSerializationAllowed = 1;

  {
    cudaLaunchConfig_t cfg = {};
    cfg.gridDim  = dim3(BB, 4);
    cfg.blockDim = dim3(256);
    cfg.stream   = 0;
    cfg.attrs    = attr;
    cfg.numAttrs = 1;
    cudaLaunchKernelEx(&cfg, scores_kernel, p_att, b_h2att, w_alpha);
  }
  {
    cudaLaunchConfig_t cfg = {};
    cfg.gridDim  = dim3(BB, 4);
    cfg.blockDim = dim3(256);
    cfg.stream   = 0;
    cfg.attrs    = attr;
    cfg.numAttrs = 1;
    cudaLaunchKernelEx(&cfg, wsum_kernel, att_feats, out);
  }
}